// round 1
// baseline (speedup 1.0000x reference)
#include <cuda_runtime.h>
#include <math.h>

#define Kc 128
#define Df 512
#define Lf 64
#define Nn 4096

// ln(2*pi) * 512
#define CONST_TERM 940.9930580015849f

// Scratch (device globals — no allocation allowed)
__device__ __align__(16) float g_W[Kc * Df * Lf];     // 16 MB: W = diag(iD)A C^-T
__device__ __align__(16) float g_iD[Kc * Df];
__device__ __align__(16) float g_iDMU[Kc * Df];
__device__ __align__(16) float g_kw[Kc * Lf];         // W^T MU
__device__ __align__(16) float g_coef[Kc];            // PI - 0.5*(const + logdetSigma + c1)
__device__ __align__(16) float g_PC[(size_t)Nn * Kc]; // per-component log densities

// ---------------------------------------------------------------------------
// Prep: per k (one block): iD, Lmat = I + A^T diag(iD) A, Cholesky, W, kw, coef
// ---------------------------------------------------------------------------
__global__ __launch_bounds__(256) void prep_kernel(const float* __restrict__ A,
                                                   const float* __restrict__ MU,
                                                   const float* __restrict__ Dm,
                                                   const float* __restrict__ PI)
{
    __shared__ float sLM[64][65];
    __shared__ float siD[512];
    __shared__ float sArow[4][64];
    __shared__ float scinv[64];
    __shared__ float sred[256];
    __shared__ float s_c1, s_slog;

    const int k = blockIdx.x;
    const int tid = threadIdx.x;

    // ---- phase 1: iD, iD*MU, c1 = sum iD mu^2, slog = sum log iD ----
    float c1p = 0.f, slp = 0.f;
    for (int d = tid; d < Df; d += 256) {
        float dv = Dm[k * Df + d];
        float id = 1.f / (dv * dv);
        siD[d] = id;
        g_iD[k * Df + d] = id;
        float mu = MU[k * Df + d];
        g_iDMU[k * Df + d] = id * mu;
        c1p += id * mu * mu;
        slp += logf(id);
    }
    sred[tid] = c1p; __syncthreads();
    for (int s = 128; s > 0; s >>= 1) { if (tid < s) sred[tid] += sred[tid + s]; __syncthreads(); }
    if (tid == 0) s_c1 = sred[0];
    __syncthreads();
    sred[tid] = slp; __syncthreads();
    for (int s = 128; s > 0; s >>= 1) { if (tid < s) sred[tid] += sred[tid + s]; __syncthreads(); }
    if (tid == 0) s_slog = sred[0];
    __syncthreads();

    // ---- phase 2: Lmat[l][m] = I + sum_d A[d,l]*iD[d]*A[d,m] ----
    const int tl = (tid >> 4) << 2;   // 16 tiles of 4 in l
    const int tm = (tid & 15) << 2;   // 16 tiles of 4 in m
    float lacc[4][4];
#pragma unroll
    for (int i = 0; i < 4; i++)
#pragma unroll
        for (int j = 0; j < 4; j++) lacc[i][j] = 0.f;

    for (int d0 = 0; d0 < Df; d0 += 4) {
        sArow[tid >> 6][tid & 63] = A[((size_t)k * Df + d0 + (tid >> 6)) * Lf + (tid & 63)];
        __syncthreads();
#pragma unroll
        for (int dd = 0; dd < 4; dd++) {
            float idv = siD[d0 + dd];
            float la[4], lb[4];
#pragma unroll
            for (int i = 0; i < 4; i++) la[i] = sArow[dd][tl + i];
#pragma unroll
            for (int j = 0; j < 4; j++) lb[j] = sArow[dd][tm + j] * idv;
#pragma unroll
            for (int i = 0; i < 4; i++)
#pragma unroll
                for (int j = 0; j < 4; j++) lacc[i][j] += la[i] * lb[j];
        }
        __syncthreads();
    }
#pragma unroll
    for (int i = 0; i < 4; i++)
#pragma unroll
        for (int j = 0; j < 4; j++)
            sLM[tl + i][tm + j] = lacc[i][j] + ((tl + i) == (tm + j) ? 1.f : 0.f);
    __syncthreads();

    // ---- phase 3: left-looking Cholesky of sLM (lower) ----
    for (int j = 0; j < 64; j++) {
        if (tid >= j && tid < 64) {
            float s = sLM[tid][j];
            for (int p = 0; p < j; p++) s -= sLM[tid][p] * sLM[j][p];
            sLM[tid][j] = s;
        }
        __syncthreads();
        if (tid == 0) {
            float dv = sqrtf(sLM[j][j]);
            sLM[j][j] = dv;
            scinv[j] = 1.f / dv;
        }
        __syncthreads();
        if (tid > j && tid < 64) sLM[tid][j] *= scinv[j];
        __syncthreads();
    }

    if (tid == 0) {
        float ld = 0.f;
        for (int j = 0; j < 64; j++) ld += logf(sLM[j][j]);
        ld *= 2.f; // log det Lmat
        float logdetSigma = ld - s_slog;
        g_coef[k] = PI[k] - 0.5f * (CONST_TERM + logdetSigma + s_c1);
    }

    // ---- phase 4: W rows via forward substitution: C w = iD[d]*A[d,:] ----
    for (int d = tid; d < Df; d += 256) {
        float idv = siD[d];
        const float* arow = A + ((size_t)k * Df + d) * Lf;
        float wv[64];
#pragma unroll
        for (int i = 0; i < 64; i++) {
            float s = arow[i] * idv;
#pragma unroll
            for (int p = 0; p < i; p++) s -= sLM[i][p] * wv[p];
            wv[i] = s * scinv[i];
        }
        float* wout = g_W + ((size_t)k * Df + d) * Lf;
#pragma unroll
        for (int i = 0; i < 64; i++) wout[i] = wv[i];
    }
    __syncthreads();

    // ---- phase 5: kw[l] = sum_d MU[d] * W[d][l] ----
    if (tid < 64) {
        float s = 0.f;
        for (int d = 0; d < Df; d++)
            s += MU[k * Df + d] * g_W[((size_t)k * Df + d) * Lf + tid];
        g_kw[k * Lf + tid] = s;
    }
}

// ---------------------------------------------------------------------------
// Main: per (k, 128-n tile): S = x @ W_k, q1 terms folded; emit per-comp logdens
// ---------------------------------------------------------------------------
__global__ __launch_bounds__(256) void main_kernel(const float* __restrict__ x)
{
    __shared__ __align__(16) float sX[16][128];
    __shared__ __align__(16) float sW[16][64];
    __shared__ float siDc[16], siMc[16];
    __shared__ float sred[128][17];

    const int k = blockIdx.y;
    const int n0 = blockIdx.x << 7;
    const int tid = threadIdx.x;
    const int tx = tid & 15;      // l dim: 16 x 4
    const int ty = tid >> 4;      // n dim: 16 x 8

    float acc[8][4];
#pragma unroll
    for (int i = 0; i < 8; i++)
#pragma unroll
        for (int j = 0; j < 4; j++) acc[i][j] = 0.f;
    float ap[8], bp[8];
#pragma unroll
    for (int i = 0; i < 8; i++) { ap[i] = 0.f; bp[i] = 0.f; }

    float kwf[4];
#pragma unroll
    for (int j = 0; j < 4; j++) kwf[j] = g_kw[k * Lf + (tx << 2) + j];

    const int nn = tid >> 1;
    const int db = (tid & 1) << 3;
    const float* xg = x + (size_t)(n0 + nn) * Df + db;

    for (int d0 = 0; d0 < Df; d0 += 16) {
        // load X tile (transposed into sX[dd][n])
        float4 v0 = *(const float4*)(xg + d0);
        float4 v1 = *(const float4*)(xg + d0 + 4);
        sX[db + 0][nn] = v0.x; sX[db + 1][nn] = v0.y;
        sX[db + 2][nn] = v0.z; sX[db + 3][nn] = v0.w;
        sX[db + 4][nn] = v1.x; sX[db + 5][nn] = v1.y;
        sX[db + 6][nn] = v1.z; sX[db + 7][nn] = v1.w;
        // load W tile
        {
            int dd = tid >> 4, ll = (tid & 15) << 2;
            *(float4*)&sW[dd][ll] =
                *(const float4*)&g_W[((size_t)k * Df + d0 + dd) * Lf + ll];
        }
        if (tid < 16) siDc[tid] = g_iD[k * Df + d0 + tid];
        else if (tid < 32) siMc[tid - 16] = g_iDMU[k * Df + d0 + (tid - 16)];
        __syncthreads();

#pragma unroll
        for (int dd = 0; dd < 16; dd++) {
            float4 xa = *(const float4*)&sX[dd][ty << 3];
            float4 xb = *(const float4*)&sX[dd][(ty << 3) + 4];
            float4 wq = *(const float4*)&sW[dd][tx << 2];
            float xv[8] = {xa.x, xa.y, xa.z, xa.w, xb.x, xb.y, xb.z, xb.w};
            float wv[4] = {wq.x, wq.y, wq.z, wq.w};
#pragma unroll
            for (int i = 0; i < 8; i++)
#pragma unroll
                for (int j = 0; j < 4; j++) acc[i][j] += xv[i] * wv[j];
        }
        // q1 terms: each thread handles dd == tx (uniform work, no divergence)
        {
            float idv = siDc[tx], imv = siMc[tx];
            float4 xa = *(const float4*)&sX[tx][ty << 3];
            float4 xb = *(const float4*)&sX[tx][(ty << 3) + 4];
            float xv[8] = {xa.x, xa.y, xa.z, xa.w, xb.x, xb.y, xb.z, xb.w};
#pragma unroll
            for (int i = 0; i < 8; i++) {
                ap[i] += xv[i] * xv[i] * idv;
                bp[i] += xv[i] * imv;
            }
        }
        __syncthreads();
    }

    // q2 partials: sum_j (acc - kw)^2
    float q2p[8];
#pragma unroll
    for (int i = 0; i < 8; i++) {
        float s = 0.f;
#pragma unroll
        for (int j = 0; j < 4; j++) {
            float dlt = acc[i][j] - kwf[j];
            s += dlt * dlt;
        }
        q2p[i] = s;
    }

    // cross-tx reductions of ap, bp, q2p
    float aa = 0.f, bb = 0.f, qq = 0.f;
#pragma unroll
    for (int i = 0; i < 8; i++) sred[(ty << 3) + i][tx] = ap[i];
    __syncthreads();
    if (tid < 128) {
#pragma unroll
        for (int p = 0; p < 16; p++) aa += sred[tid][p];
    }
    __syncthreads();
#pragma unroll
    for (int i = 0; i < 8; i++) sred[(ty << 3) + i][tx] = bp[i];
    __syncthreads();
    if (tid < 128) {
#pragma unroll
        for (int p = 0; p < 16; p++) bb += sred[tid][p];
    }
    __syncthreads();
#pragma unroll
    for (int i = 0; i < 8; i++) sred[(ty << 3) + i][tx] = q2p[i];
    __syncthreads();
    if (tid < 128) {
#pragma unroll
        for (int p = 0; p < 16; p++) qq += sred[tid][p];
        // m_d = (aa - 2bb + c1) - qq ; c1 folded into coef
        float pc = g_coef[k] - 0.5f * (aa - 2.f * bb - qq);
        g_PC[(size_t)(n0 + tid) * Kc + k] = pc;
    }
}

// ---------------------------------------------------------------------------
// Logsumexp over K per n (warp per n)
// ---------------------------------------------------------------------------
__global__ __launch_bounds__(256) void lse_kernel(float* __restrict__ out)
{
    const int tid = threadIdx.x;
    const int n = blockIdx.x * 8 + (tid >> 5);
    const int lane = tid & 31;
    float4 v = ((const float4*)(g_PC + (size_t)n * Kc))[lane];
    float mx = fmaxf(fmaxf(v.x, v.y), fmaxf(v.z, v.w));
#pragma unroll
    for (int o = 16; o; o >>= 1) mx = fmaxf(mx, __shfl_xor_sync(0xffffffffu, mx, o));
    float s = expf(v.x - mx) + expf(v.y - mx) + expf(v.z - mx) + expf(v.w - mx);
#pragma unroll
    for (int o = 16; o; o >>= 1) s += __shfl_xor_sync(0xffffffffu, s, o);
    if (lane == 0) out[n] = mx + logf(s);
}

extern "C" void kernel_launch(void* const* d_in, const int* in_sizes, int n_in,
                              void* d_out, int out_size)
{
    const float* x  = (const float*)d_in[0];
    const float* MU = (const float*)d_in[1];
    const float* A  = (const float*)d_in[2];
    const float* Dm = (const float*)d_in[3];
    const float* PI = (const float*)d_in[4];
    float* out = (float*)d_out;

    prep_kernel<<<Kc, 256>>>(A, MU, Dm, PI);
    dim3 grid(Nn / 128, Kc);
    main_kernel<<<grid, 256>>>(x);
    lse_kernel<<<Nn / 8, 256>>>(out);
}

// round 2
// speedup vs baseline: 1.3071x; 1.3071x over previous
#include <cuda_runtime.h>
#include <math.h>

#define Kc 128
#define Df 512
#define Lf 64
#define Nn 4096

// ln(2*pi) * 512
#define CONST_TERM 940.9930580015849f

typedef unsigned long long ull;

// packed f32x2 helpers (sm_100+ PTX)
#define FMA2(acc, a, b) asm("fma.rn.f32x2 %0, %1, %2, %0;" : "+l"(acc) : "l"(a), "l"(b))
#define MUL2(d, a, b)   asm("mul.rn.f32x2 %0, %1, %2;" : "=l"(d) : "l"(a), "l"(b))
#define ADD2(d, a, b)   asm("add.rn.f32x2 %0, %1, %2;" : "=l"(d) : "l"(a), "l"(b))

__device__ __forceinline__ ull pk(float v) {
    ull r; asm("mov.b64 %0, {%1, %1};" : "=l"(r) : "f"(v)); return r;
}
__device__ __forceinline__ float2 u2f(ull u) {
    float2 f; asm("mov.b64 {%0, %1}, %2;" : "=f"(f.x), "=f"(f.y) : "l"(u)); return f;
}

// Scratch (device globals — no allocation allowed)
__device__ __align__(16) float g_W[Kc * Df * Lf];     // 16 MB: W = diag(iD)A C^-T
__device__ __align__(16) float g_iD[Kc * Df];
__device__ __align__(16) float g_iDMU[Kc * Df];
__device__ __align__(16) float g_nkw[Kc * Lf];        // -(W^T MU)
__device__ __align__(16) float g_coef[Kc];            // PI - 0.5*(const + logdetSigma + c1)
__device__ __align__(16) float g_PC[(size_t)Nn * Kc]; // per-component log densities

// ---------------------------------------------------------------------------
// Prep: per k (one block): iD, Lmat = I + A^T diag(iD) A, Cholesky, Cinv,
// W = (iD*A) @ Cinv^T (tiled GEMM, no register spills), nkw, coef
// ---------------------------------------------------------------------------
__global__ __launch_bounds__(256) void prep_kernel(const float* __restrict__ A,
                                                   const float* __restrict__ MU,
                                                   const float* __restrict__ Dm,
                                                   const float* __restrict__ PI)
{
    // sLMb: holds Lmat/C (stride 65) during phases 2-4, reused as B tile (stride 68) in phase 5
    __shared__ float sLMb[64 * 68];
    __shared__ float sCIT[64 * 68];   // sCIT[j*68+i] = Cinv[i][j]
    __shared__ float siD[512];
    __shared__ float siMU[512];
    __shared__ float sArow[4 * 64];
    __shared__ float scinv[64];
    __shared__ float sv[64];
    __shared__ float sred[256];
    __shared__ float s_c1, s_slog;

    const int k = blockIdx.x;
    const int tid = threadIdx.x;

#define LM(i, j) sLMb[(i) * 65 + (j)]

    // ---- phase 1: iD, iD*MU, c1 = sum iD mu^2, slog = sum log iD ----
    float c1p = 0.f, slp = 0.f;
    for (int d = tid; d < Df; d += 256) {
        float dv = Dm[k * Df + d];
        float id = 1.f / (dv * dv);
        siD[d] = id;
        g_iD[k * Df + d] = id;
        float mu = MU[k * Df + d];
        float im = id * mu;
        siMU[d] = im;
        g_iDMU[k * Df + d] = im;
        c1p += im * mu;
        slp += logf(id);
    }
    sred[tid] = c1p; __syncthreads();
    for (int s = 128; s > 0; s >>= 1) { if (tid < s) sred[tid] += sred[tid + s]; __syncthreads(); }
    if (tid == 0) s_c1 = sred[0];
    __syncthreads();
    sred[tid] = slp; __syncthreads();
    for (int s = 128; s > 0; s >>= 1) { if (tid < s) sred[tid] += sred[tid + s]; __syncthreads(); }
    if (tid == 0) s_slog = sred[0];
    __syncthreads();

    // ---- phase 2: Lmat[l][m] = I + sum_d A[d,l]*iD[d]*A[d,m], v[p] = sum_d iDMU[d] A[d,p] ----
    const int tl = (tid >> 4) << 2;
    const int tm = (tid & 15) << 2;
    float lacc[4][4];
#pragma unroll
    for (int i = 0; i < 4; i++)
#pragma unroll
        for (int j = 0; j < 4; j++) lacc[i][j] = 0.f;
    float vacc = 0.f;

    for (int d0 = 0; d0 < Df; d0 += 4) {
        sArow[(tid >> 6) * 64 + (tid & 63)] = A[((size_t)k * Df + d0 + (tid >> 6)) * Lf + (tid & 63)];
        __syncthreads();
#pragma unroll
        for (int dd = 0; dd < 4; dd++) {
            float idv = siD[d0 + dd];
            float la[4], lb[4];
#pragma unroll
            for (int i = 0; i < 4; i++) la[i] = sArow[dd * 64 + tl + i];
#pragma unroll
            for (int j = 0; j < 4; j++) lb[j] = sArow[dd * 64 + tm + j] * idv;
#pragma unroll
            for (int i = 0; i < 4; i++)
#pragma unroll
                for (int j = 0; j < 4; j++) lacc[i][j] += la[i] * lb[j];
        }
        if (tid < 64) {
#pragma unroll
            for (int dd = 0; dd < 4; dd++)
                vacc += siMU[d0 + dd] * sArow[dd * 64 + tid];
        }
        __syncthreads();
    }
#pragma unroll
    for (int i = 0; i < 4; i++)
#pragma unroll
        for (int j = 0; j < 4; j++)
            LM(tl + i, tm + j) = lacc[i][j] + ((tl + i) == (tm + j) ? 1.f : 0.f);
    if (tid < 64) sv[tid] = vacc;
    __syncthreads();

    // ---- phase 3: left-looking Cholesky of LM (lower) ----
    for (int j = 0; j < 64; j++) {
        if (tid >= j && tid < 64) {
            float s = LM(tid, j);
            for (int p = 0; p < j; p++) s -= LM(tid, p) * LM(j, p);
            LM(tid, j) = s;
        }
        __syncthreads();
        if (tid == 0) {
            float dv = sqrtf(LM(j, j));
            LM(j, j) = dv;
            scinv[j] = 1.f / dv;
        }
        __syncthreads();
        if (tid > j && tid < 64) LM(tid, j) *= scinv[j];
        __syncthreads();
    }

    if (tid == 0) {
        float ld = 0.f;
        for (int j = 0; j < 64; j++) ld += logf(LM(j, j));
        ld *= 2.f; // log det Lmat
        float logdetSigma = ld - s_slog;
        g_coef[k] = PI[k] - 0.5f * (CONST_TERM + logdetSigma + s_c1);
    }

    // ---- phase 4: Cinv (lower triangular inverse), columns in parallel, all in smem ----
    for (int idx = tid; idx < 64 * 68; idx += 256) sCIT[idx] = 0.f;
    __syncthreads();
    if (tid < 64) {
        const int j = tid;
        for (int i = j; i < 64; i++) {
            float s = (i == j) ? 1.f : 0.f;
            for (int p = j; p < i; p++) s -= LM(i, p) * sCIT[j * 68 + p];
            sCIT[j * 68 + i] = s * scinv[i];
        }
    }
    __syncthreads();

    // nkw[l] = -sum_p Cinv[l][p] v[p]
    if (tid < 64) {
        float s = 0.f;
        for (int p = 0; p < 64; p++) s += sCIT[p * 68 + tid] * sv[p];
        g_nkw[k * Lf + tid] = -s;
    }
    __syncthreads();   // LM no longer needed; safe to overwrite with B tiles

    // ---- phase 5: W = B @ Cinv^T, B = iD*A, tiled 64 rows at a time ----
    const int td = (tid >> 4) << 2;
    const int tcl = (tid & 15) << 2;
    const int lr = tid >> 2;            // load row 0..63
    const int lc = (tid & 3) << 4;      // load col 0,16,32,48
    for (int dt = 0; dt < 8; dt++) {
        // load B tile into sLMb (stride 68)
        {
            float idv = siD[dt * 64 + lr];
            const float* ar = A + ((size_t)k * Df + dt * 64 + lr) * Lf + lc;
#pragma unroll
            for (int q = 0; q < 4; q++) {
                float4 av = *(const float4*)(ar + 4 * q);
                av.x *= idv; av.y *= idv; av.z *= idv; av.w *= idv;
                *(float4*)&sLMb[lr * 68 + lc + 4 * q] = av;
            }
        }
        __syncthreads();
        float wacc[4][4];
#pragma unroll
        for (int i = 0; i < 4; i++)
#pragma unroll
            for (int j = 0; j < 4; j++) wacc[i][j] = 0.f;
        for (int p = 0; p < 64; p++) {
            float la[4];
#pragma unroll
            for (int i = 0; i < 4; i++) la[i] = sLMb[(td + i) * 68 + p];
            float4 lcv = *(const float4*)&sCIT[p * 68 + tcl];   // Cinv[tcl..+3][p]
            float lcj[4] = {lcv.x, lcv.y, lcv.z, lcv.w};
#pragma unroll
            for (int i = 0; i < 4; i++)
#pragma unroll
                for (int j = 0; j < 4; j++) wacc[i][j] += la[i] * lcj[j];
        }
#pragma unroll
        for (int i = 0; i < 4; i++) {
            float4 wv = make_float4(wacc[i][0], wacc[i][1], wacc[i][2], wacc[i][3]);
            *(float4*)&g_W[((size_t)k * Df + dt * 64 + td + i) * Lf + tcl] = wv;
        }
        __syncthreads();
    }
#undef LM
}

// ---------------------------------------------------------------------------
// Main: per (k, 128-n tile): t = x @ W_k via packed f32x2 FMA; q1 folded.
// 128 threads, 8n x 8l register tiles (accumulators packed along l).
// ---------------------------------------------------------------------------
#define SXP 136
__global__ __launch_bounds__(128) void main_kernel(const float* __restrict__ x)
{
    __shared__ __align__(16) float sXf[16 * SXP];
    __shared__ __align__(16) float sW[16 * 64];
    __shared__ float siDc[16], siMc[16];

    const int k = blockIdx.y;
    const int n0 = blockIdx.x << 7;
    const int tid = threadIdx.x;
    const int tx = tid & 7;
    const int tx8 = tx << 3;
    const int ty8 = (tid >> 3) << 3;

    ull acc2[8][4];
#pragma unroll
    for (int i = 0; i < 8; i++)
#pragma unroll
        for (int j = 0; j < 4; j++) acc2[i][j] = 0ULL;
    ull ap2[4] = {0ULL, 0ULL, 0ULL, 0ULL};
    ull bp2[4] = {0ULL, 0ULL, 0ULL, 0ULL};

    const int ldn = tid >> 2;          // 0..31
    const int ldd = (tid & 3) << 2;    // 0,4,8,12
    const float* xbase = x + (size_t)n0 * Df;
    const float* wbase = g_W + ((size_t)k * Df) * Lf;

    for (int d0 = 0; d0 < Df; d0 += 16) {
        // x tile -> sXf (transposed, pad 136), coalesced 64B segments
#pragma unroll
        for (int pass = 0; pass < 4; pass++) {
            int n = (pass << 5) + ldn;
            float4 v = *(const float4*)(xbase + (size_t)n * Df + d0 + ldd);
            sXf[(ldd + 0) * SXP + n] = v.x;
            sXf[(ldd + 1) * SXP + n] = v.y;
            sXf[(ldd + 2) * SXP + n] = v.z;
            sXf[(ldd + 3) * SXP + n] = v.w;
        }
        // W tile flat copy (same layout)
        {
            const float4* src = (const float4*)(wbase + (size_t)d0 * Lf);
            float4* dst = (float4*)sW;
            dst[tid] = src[tid];
            dst[tid + 128] = src[tid + 128];
        }
        if (tid < 16) siDc[tid] = g_iD[k * Df + d0 + tid];
        else if (tid < 32) siMc[tid - 16] = g_iDMU[k * Df + d0 + tid - 16];
        __syncthreads();

#pragma unroll
        for (int dd = 0; dd < 16; dd++) {
            const float* xr = &sXf[dd * SXP + ty8];
            float4 xa = *(const float4*)xr;
            float4 xb = *(const float4*)(xr + 4);
            ulonglong2 wA = *(const ulonglong2*)&sW[dd * 64 + tx8];
            ulonglong2 wB = *(const ulonglong2*)&sW[dd * 64 + tx8 + 4];
            ull xd;
            xd = pk(xa.x);
            FMA2(acc2[0][0], xd, wA.x); FMA2(acc2[0][1], xd, wA.y);
            FMA2(acc2[0][2], xd, wB.x); FMA2(acc2[0][3], xd, wB.y);
            xd = pk(xa.y);
            FMA2(acc2[1][0], xd, wA.x); FMA2(acc2[1][1], xd, wA.y);
            FMA2(acc2[1][2], xd, wB.x); FMA2(acc2[1][3], xd, wB.y);
            xd = pk(xa.z);
            FMA2(acc2[2][0], xd, wA.x); FMA2(acc2[2][1], xd, wA.y);
            FMA2(acc2[2][2], xd, wB.x); FMA2(acc2[2][3], xd, wB.y);
            xd = pk(xa.w);
            FMA2(acc2[3][0], xd, wA.x); FMA2(acc2[3][1], xd, wA.y);
            FMA2(acc2[3][2], xd, wB.x); FMA2(acc2[3][3], xd, wB.y);
            xd = pk(xb.x);
            FMA2(acc2[4][0], xd, wA.x); FMA2(acc2[4][1], xd, wA.y);
            FMA2(acc2[4][2], xd, wB.x); FMA2(acc2[4][3], xd, wB.y);
            xd = pk(xb.y);
            FMA2(acc2[5][0], xd, wA.x); FMA2(acc2[5][1], xd, wA.y);
            FMA2(acc2[5][2], xd, wB.x); FMA2(acc2[5][3], xd, wB.y);
            xd = pk(xb.z);
            FMA2(acc2[6][0], xd, wA.x); FMA2(acc2[6][1], xd, wA.y);
            FMA2(acc2[6][2], xd, wB.x); FMA2(acc2[6][3], xd, wB.y);
            xd = pk(xb.w);
            FMA2(acc2[7][0], xd, wA.x); FMA2(acc2[7][1], xd, wA.y);
            FMA2(acc2[7][2], xd, wB.x); FMA2(acc2[7][3], xd, wB.y);
        }

        // q1 terms (packed along n): this thread handles dd = tx and tx+8
#pragma unroll
        for (int h = 0; h < 2; h++) {
            int dd = tx + (h << 3);
            const float* xr = &sXf[dd * SXP + ty8];
            ulonglong2 xpA = *(const ulonglong2*)xr;
            ulonglong2 xpB = *(const ulonglong2*)(xr + 4);
            ull idp = pk(siDc[dd]);
            ull imp = pk(siMc[dd]);
            ull u;
            MUL2(u, xpA.x, xpA.x); FMA2(ap2[0], u, idp); FMA2(bp2[0], xpA.x, imp);
            MUL2(u, xpA.y, xpA.y); FMA2(ap2[1], u, idp); FMA2(bp2[1], xpA.y, imp);
            MUL2(u, xpB.x, xpB.x); FMA2(ap2[2], u, idp); FMA2(bp2[2], xpB.x, imp);
            MUL2(u, xpB.y, xpB.y); FMA2(ap2[3], u, idp); FMA2(bp2[3], xpB.y, imp);
        }
        __syncthreads();
    }

    // epilogue: r[i] = (aa - 2bb) - q2 for this thread's slice, then reduce over tx
    ulonglong2 nk0 = *(const ulonglong2*)&g_nkw[k * Lf + tx8];
    ulonglong2 nk1 = *(const ulonglong2*)&g_nkw[k * Lf + tx8 + 4];
    ull nkw[4] = {nk0.x, nk0.y, nk1.x, nk1.y};

    float r[8];
#pragma unroll
    for (int i = 0; i < 8; i++) {
        ull s2 = 0ULL;
#pragma unroll
        for (int j = 0; j < 4; j++) {
            ull d2;
            ADD2(d2, acc2[i][j], nkw[j]);
            FMA2(s2, d2, d2);
        }
        float2 f = u2f(s2);
        r[i] = -(f.x + f.y);
    }
#pragma unroll
    for (int p = 0; p < 4; p++) {
        float2 a = u2f(ap2[p]);
        float2 b = u2f(bp2[p]);
        r[2 * p]     += a.x - 2.f * b.x;
        r[2 * p + 1] += a.y - 2.f * b.y;
    }
#pragma unroll
    for (int i = 0; i < 8; i++) {
#pragma unroll
        for (int o = 1; o < 8; o <<= 1)
            r[i] += __shfl_xor_sync(0xffffffffu, r[i], o);
    }
    if (tx == 0) {
        float coef = g_coef[k];
#pragma unroll
        for (int i = 0; i < 8; i++)
            g_PC[(size_t)(n0 + ty8 + i) * Kc + k] = coef - 0.5f * r[i];
    }
}

// ---------------------------------------------------------------------------
// Logsumexp over K per n (warp per n)
// ---------------------------------------------------------------------------
__global__ __launch_bounds__(256) void lse_kernel(float* __restrict__ out)
{
    const int tid = threadIdx.x;
    const int n = blockIdx.x * 8 + (tid >> 5);
    const int lane = tid & 31;
    float4 v = ((const float4*)(g_PC + (size_t)n * Kc))[lane];
    float mx = fmaxf(fmaxf(v.x, v.y), fmaxf(v.z, v.w));
#pragma unroll
    for (int o = 16; o; o >>= 1) mx = fmaxf(mx, __shfl_xor_sync(0xffffffffu, mx, o));
    float s = expf(v.x - mx) + expf(v.y - mx) + expf(v.z - mx) + expf(v.w - mx);
#pragma unroll
    for (int o = 16; o; o >>= 1) s += __shfl_xor_sync(0xffffffffu, s, o);
    if (lane == 0) out[n] = mx + logf(s);
}

extern "C" void kernel_launch(void* const* d_in, const int* in_sizes, int n_in,
                              void* d_out, int out_size)
{
    const float* x  = (const float*)d_in[0];
    const float* MU = (const float*)d_in[1];
    const float* A  = (const float*)d_in[2];
    const float* Dm = (const float*)d_in[3];
    const float* PI = (const float*)d_in[4];
    float* out = (float*)d_out;

    prep_kernel<<<Kc, 256>>>(A, MU, Dm, PI);
    dim3 grid(Nn / 128, Kc);
    main_kernel<<<grid, 128>>>(x);
    lse_kernel<<<Nn / 8, 256>>>(out);
}